// round 1
// baseline (speedup 1.0000x reference)
#include <cuda_runtime.h>
#include <cstdint>

// ---------------------------------------------------------------------------
// GMP_34196529611440 : generalized memory polynomial
//   y[n] = sum_{k,l} a[k,l] x[n-l] |x[n-l]|^k
//        + sum_{k,l,m} b[k,l,m] x[n-l] |x[n-l-m]|^k
//        + sum_{k,l,m} c[k,l,m] x[n-l] |x[n-l+m]|^k
//   Ka=5,La=4; Kb=4,Lb=3,Mb=4; Kc=4,Lc=3,Mc=4; indices clipped to [0,N-1]
// Output: [2,N] float32 (re plane then im plane)
// ---------------------------------------------------------------------------

typedef unsigned long long u64;

// packed merged coefficients (complex as {re,im} float2):
//  E[l][k]  l=0..3, k=0..4 : a[k,l] (+ b[k,l,0]+c[k,l,0] for l<3,k<4)   idx = l*5+k        [0..19]
//  B[l][m-1][k] l=0..2, m=1..3, k=0..3 : b[k,l,m]                       idx = 20+(l*3+m-1)*4+k [20..55]
//  C[l][m-1][k]                                                         idx = 56+(l*3+m-1)*4+k [56..91]
__device__ float2 g_coef[92];

__global__ void gmp_prep(const float* __restrict__ a_re, const float* __restrict__ a_im,
                         const float* __restrict__ b_re, const float* __restrict__ b_im,
                         const float* __restrict__ c_re, const float* __restrict__ c_im) {
    if (threadIdx.x == 0 && blockIdx.x == 0) {
        // a: [5,4]  a[k*4+l] ; b,c: [4,3,4]  b[(k*3+l)*4+m]
        for (int l = 0; l < 4; ++l)
            for (int k = 0; k < 5; ++k) {
                float re = a_re[k * 4 + l];
                float im = a_im[k * 4 + l];
                if (l < 3 && k < 4) {
                    re += b_re[(k * 3 + l) * 4 + 0] + c_re[(k * 3 + l) * 4 + 0];
                    im += b_im[(k * 3 + l) * 4 + 0] + c_im[(k * 3 + l) * 4 + 0];
                }
                g_coef[l * 5 + k] = make_float2(re, im);
            }
        for (int l = 0; l < 3; ++l)
            for (int m = 1; m < 4; ++m)
                for (int k = 0; k < 4; ++k) {
                    int src = (k * 3 + l) * 4 + m;
                    g_coef[20 + (l * 3 + (m - 1)) * 4 + k] = make_float2(b_re[src], b_im[src]);
                    g_coef[56 + (l * 3 + (m - 1)) * 4 + k] = make_float2(c_re[src], c_im[src]);
                }
    }
}

// ---- packed f32x2 helpers (Blackwell FFMA2 path, PTX-only per SASS_QUICKREF)
__device__ __forceinline__ u64 fma2(u64 a, u64 b, u64 c) {
    u64 d;
    asm("fma.rn.f32x2 %0, %1, %2, %3;" : "=l"(d) : "l"(a), "l"(b), "l"(c));
    return d;
}
__device__ __forceinline__ u64 add2(u64 a, u64 b) {
    u64 d;
    asm("add.rn.f32x2 %0, %1, %2;" : "=l"(d) : "l"(a), "l"(b));
    return d;
}
__device__ __forceinline__ u64 pack2(float x, float y) {
    u64 r;
    asm("mov.b64 %0, {%1, %2};" : "=l"(r) : "f"(x), "f"(y));
    return r;
}
__device__ __forceinline__ void unpack2(u64 v, float& x, float& y) {
    asm("mov.b64 {%0, %1}, %2;" : "=f"(x), "=f"(y) : "l"(v));
}
__device__ __forceinline__ float sqrt_approx(float s) {
    float r;
    asm("sqrt.approx.f32 %0, %1;" : "=f"(r) : "f"(s));
    return r;
}

constexpr int ITER = 4;   // samples per thread
constexpr int TPB  = 256; // threads per block

__global__ __launch_bounds__(TPB)
void gmp_kernel(const float* __restrict__ xre, const float* __restrict__ xim,
                float* __restrict__ out, int N) {
    __shared__ float2 scf[92];
    const int tid = threadIdx.x;
    if (tid < 92) scf[tid] = g_coef[tid];
    __syncthreads();
    const u64* sc = reinterpret_cast<const u64*>(scf);

    const int n0 = (blockIdx.x * TPB + tid) * ITER;
    if (n0 >= N) return;

    // ---- window: |x| at n0-5 .. n0+ITER+2 (12), x at n0-3 .. n0+ITER-1 (7)
    constexpr int W = ITER + 8;
    u64   pp2[W];        // duplicated {p,p} pairs for f32x2 Horner
    float xr[ITER + 3], xi[ITER + 3];
#pragma unroll
    for (int j = 0; j < W; ++j) {
        int idx = n0 + j - 5;
        idx = max(idx, 0);
        idx = min(idx, N - 1);
        float r = xre[idx];
        float i = xim[idx];
        float p = sqrt_approx(fmaf(r, r, i * i));
        pp2[j] = pack2(p, p);
        if (j >= 2 && j < 2 + ITER + 3) { xr[j - 2] = r; xi[j - 2] = i; }
    }

    // ---- accumulators w[l][it] (complex, packed)
    u64 w[4][ITER];
#pragma unroll
    for (int l = 0; l < 4; ++l)
#pragma unroll
        for (int it = 0; it < ITER; ++it) w[l][it] = 0ull;

    // ---- merged degree-4 polys E[l] at p[n+it-l]
#pragma unroll
    for (int l = 0; l < 4; ++l) {
        const u64 c0 = sc[l * 5 + 0], c1 = sc[l * 5 + 1], c2 = sc[l * 5 + 2],
                  c3 = sc[l * 5 + 3], c4 = sc[l * 5 + 4];
#pragma unroll
        for (int it = 0; it < ITER; ++it) {
            const u64 p = pp2[it - l + 5];
            u64 t = fma2(c4, p, c3);
            t = fma2(t, p, c2);
            t = fma2(t, p, c1);
            t = fma2(t, p, c0);
            w[l][it] = add2(w[l][it], t);
        }
    }

    // ---- B polys (deg 3) at p[n+it-l-m], m=1..3
#pragma unroll
    for (int l = 0; l < 3; ++l)
#pragma unroll
        for (int m = 1; m < 4; ++m) {
            const int base = 20 + (l * 3 + (m - 1)) * 4;
            const u64 c0 = sc[base + 0], c1 = sc[base + 1], c2 = sc[base + 2], c3 = sc[base + 3];
#pragma unroll
            for (int it = 0; it < ITER; ++it) {
                const u64 p = pp2[it - l - m + 5];
                u64 t = fma2(c3, p, c2);
                t = fma2(t, p, c1);
                t = fma2(t, p, c0);
                w[l][it] = add2(w[l][it], t);
            }
        }

    // ---- C polys (deg 3) at p[n+it-l+m], m=1..3
#pragma unroll
    for (int l = 0; l < 3; ++l)
#pragma unroll
        for (int m = 1; m < 4; ++m) {
            const int base = 56 + (l * 3 + (m - 1)) * 4;
            const u64 c0 = sc[base + 0], c1 = sc[base + 1], c2 = sc[base + 2], c3 = sc[base + 3];
#pragma unroll
            for (int it = 0; it < ITER; ++it) {
                const u64 p = pp2[it - l + m + 5];
                u64 t = fma2(c3, p, c2);
                t = fma2(t, p, c1);
                t = fma2(t, p, c0);
                w[l][it] = add2(w[l][it], t);
            }
        }

    // ---- y[n+it] = sum_l x[n+it-l] * w[l][it]  (complex multiply-accumulate)
#pragma unroll
    for (int it = 0; it < ITER; ++it) {
        float yr = 0.f, yi = 0.f;
#pragma unroll
        for (int l = 0; l < 4; ++l) {
            float vr, vi;
            unpack2(w[l][it], vr, vi);
            const float r = xr[it - l + 3];
            const float i = xi[it - l + 3];
            yr = fmaf(r, vr, yr);
            yr = fmaf(-i, vi, yr);
            yi = fmaf(r, vi, yi);
            yi = fmaf(i, vr, yi);
        }
        const int n = n0 + it;
        if (n < N) {
            out[n] = yr;
            out[N + n] = yi;
        }
    }
}

extern "C" void kernel_launch(void* const* d_in, const int* in_sizes, int n_in,
                              void* d_out, int out_size) {
    const float* x_re = (const float*)d_in[0];
    const float* x_im = (const float*)d_in[1];
    const float* a_re = (const float*)d_in[2];
    const float* a_im = (const float*)d_in[3];
    const float* b_re = (const float*)d_in[4];
    const float* b_im = (const float*)d_in[5];
    const float* c_re = (const float*)d_in[6];
    const float* c_im = (const float*)d_in[7];
    float* out = (float*)d_out;
    const int N = in_sizes[0];

    gmp_prep<<<1, 32>>>(a_re, a_im, b_re, b_im, c_re, c_im);

    const int spb = TPB * ITER;
    const int grid = (N + spb - 1) / spb;
    gmp_kernel<<<grid, TPB>>>(x_re, x_im, out, N);
}

// round 2
// speedup vs baseline: 1.2283x; 1.2283x over previous
#include <cuda_runtime.h>
#include <cstdint>

// ---------------------------------------------------------------------------
// GMP_34196529611440 : generalized memory polynomial, single fused kernel.
//   y[n] = sum_{k,l} a[k,l] x[n-l] |x[n-l]|^k
//        + sum_{k,l,m} b[k,l,m] x[n-l] |x[n-l-m]|^k
//        + sum_{k,l,m} c[k,l,m] x[n-l] |x[n-l+m]|^k
// Algebra:
//   * m=0 terms of b,c merge into a's poly (same basis).
//   * all k=0 (constant) terms collapse into one complex c0tot[l] initializer,
//     so every poly is  w = fma2(q(p), p, w)  -- zero add2 instructions.
// ---------------------------------------------------------------------------

typedef unsigned long long u64;

__device__ __forceinline__ u64 fma2(u64 a, u64 b, u64 c) {
    u64 d;
    asm("fma.rn.f32x2 %0, %1, %2, %3;" : "=l"(d) : "l"(a), "l"(b), "l"(c));
    return d;
}
__device__ __forceinline__ u64 pack2(float x, float y) {
    u64 r;
    asm("mov.b64 %0, {%1, %2};" : "=l"(r) : "f"(x), "f"(y));
    return r;
}
__device__ __forceinline__ void unpack2(u64 v, float& x, float& y) {
    asm("mov.b64 {%0, %1}, %2;" : "=f"(x), "=f"(y) : "l"(v));
}
__device__ __forceinline__ float sqrt_approx(float s) {
    float r;
    asm("sqrt.approx.f32 %0, %1;" : "=f"(r) : "f"(s));
    return r;
}

constexpr int ITER = 4;    // samples per thread (consecutive)
constexpr int TPB  = 256;  // threads per block
constexpr int SPB  = TPB * ITER;       // samples per block
constexpr int TILE = SPB + 12;         // halo: -5 .. +6 (need -5..+3, pad)

// shared coefficient layout (complex float2 == u64):
//   [0..3]    c0tot[l]                    (all constant terms, per l)
//   [4..19]   E[l][k-1]  l=0..3, k=1..4   (a merged with b/c m=0)
//   [20..46]  B[l*9 + (m-1)*3 + (k-1)]    l=0..2, m=1..3, k=1..3
//   [47..73]  C[l*9 + (m-1)*3 + (k-1)]
constexpr int NCOEF = 74;

__global__ __launch_bounds__(TPB, 4)
void gmp_kernel(const float* __restrict__ xre, const float* __restrict__ xim,
                const float* __restrict__ a_re, const float* __restrict__ a_im,
                const float* __restrict__ b_re, const float* __restrict__ b_im,
                const float* __restrict__ c_re, const float* __restrict__ c_im,
                float* __restrict__ out, int N) {
    __shared__ float2 scoef[NCOEF];
    __shared__ float2 sxc[TILE];   // {re, im}
    __shared__ float  sp[TILE];    // |x|

    const int tid = threadIdx.x;
    const int blockStart = blockIdx.x * SPB;

    // ---- per-block coefficient merge (threads 0..73), one-time cheap work
    if (tid < NCOEF) {
        float re, im;
        if (tid < 4) {                    // c0tot[l] = a[0,l] + sum_m (b[0,l,m]+c[0,l,m])
            int l = tid;
            re = a_re[l]; im = a_im[l];   // a[0*4+l]
            if (l < 3) {
#pragma unroll
                for (int m = 0; m < 4; ++m) {   // b[(0*3+l)*4+m]
                    re += b_re[l * 4 + m] + c_re[l * 4 + m];
                    im += b_im[l * 4 + m] + c_im[l * 4 + m];
                }
            }
        } else if (tid < 20) {            // E[l][k], k=1..4
            int e = tid - 4, l = e >> 2, k = (e & 3) + 1;
            re = a_re[k * 4 + l]; im = a_im[k * 4 + l];
            if (l < 3 && k < 4) {         // merge b/c m=0
                int src = (k * 3 + l) * 4;
                re += b_re[src] + c_re[src];
                im += b_im[src] + c_im[src];
            }
        } else if (tid < 47) {            // B, k=1..3, m=1..3
            int e = tid - 20, l = e / 9, r9 = e % 9, m = r9 / 3 + 1, k = r9 % 3 + 1;
            int src = (k * 3 + l) * 4 + m;
            re = b_re[src]; im = b_im[src];
        } else {                          // C
            int e = tid - 47, l = e / 9, r9 = e % 9, m = r9 / 3 + 1, k = r9 % 3 + 1;
            int src = (k * 3 + l) * 4 + m;
            re = c_re[src]; im = c_im[src];
        }
        scoef[tid] = make_float2(re, im);
    }

    // ---- cooperative x tile load: each sample read ONCE, |x| computed ONCE
#pragma unroll
    for (int s = tid; s < TILE; s += TPB) {
        int g = blockStart - 5 + s;
        g = max(g, 0);
        g = min(g, N - 1);
        float r = xre[g];
        float i = xim[g];
        sxc[s] = make_float2(r, i);
        sp[s] = sqrt_approx(fmaf(r, r, i * i));
    }
    __syncthreads();

    const u64* sc = reinterpret_cast<const u64*>(scoef);
    const u64* sx = reinterpret_cast<const u64*>(sxc);

    const int base = tid * ITER;   // sp[base + j] == |x| at n0 + j - 5
    const int n0 = blockStart + base;

    // duplicated {p,p} window for f32x2 Horner
    u64 pp2[12];
#pragma unroll
    for (int j = 0; j < 12; ++j) {
        float p = sp[base + j];
        pp2[j] = pack2(p, p);
    }

    float yr[ITER], yi[ITER];
#pragma unroll
    for (int it = 0; it < ITER; ++it) { yr[it] = 0.f; yi[it] = 0.f; }

#pragma unroll
    for (int l = 0; l < 4; ++l) {
        // init with the folded constant terms
        u64 wl[ITER];
        {
            const u64 c0 = sc[l];
#pragma unroll
            for (int it = 0; it < ITER; ++it) wl[it] = c0;
        }
        // merged degree-4 poly at p[n+it-l]:  w = (((e4 p + e3) p + e2) p + e1) p + w
        {
            const u64 e1 = sc[4 + l * 4 + 0], e2 = sc[4 + l * 4 + 1],
                      e3 = sc[4 + l * 4 + 2], e4 = sc[4 + l * 4 + 3];
#pragma unroll
            for (int it = 0; it < ITER; ++it) {
                const u64 p = pp2[it - l + 5];
                u64 q = fma2(e4, p, e3);
                q = fma2(q, p, e2);
                q = fma2(q, p, e1);
                wl[it] = fma2(q, p, wl[it]);
            }
        }
        if (l < 3) {
#pragma unroll
            for (int m = 1; m < 4; ++m) {   // B: p[n+it-l-m]
                const int bb = 20 + l * 9 + (m - 1) * 3;
                const u64 b1 = sc[bb + 0], b2 = sc[bb + 1], b3 = sc[bb + 2];
#pragma unroll
                for (int it = 0; it < ITER; ++it) {
                    const u64 p = pp2[it - l - m + 5];
                    u64 q = fma2(b3, p, b2);
                    q = fma2(q, p, b1);
                    wl[it] = fma2(q, p, wl[it]);
                }
            }
#pragma unroll
            for (int m = 1; m < 4; ++m) {   // C: p[n+it-l+m]
                const int cb = 47 + l * 9 + (m - 1) * 3;
                const u64 c1 = sc[cb + 0], c2 = sc[cb + 1], c3 = sc[cb + 2];
#pragma unroll
                for (int it = 0; it < ITER; ++it) {
                    const u64 p = pp2[it - l + m + 5];
                    u64 q = fma2(c3, p, c2);
                    q = fma2(q, p, c1);
                    wl[it] = fma2(q, p, wl[it]);
                }
            }
        }
        // combine: y[n+it] += x[n+it-l] * w_l   (complex)
#pragma unroll
        for (int it = 0; it < ITER; ++it) {
            float vr, vi;
            unpack2(wl[it], vr, vi);
            float r, i;
            unpack2(sx[base + 5 + it - l], r, i);
            yr[it] = fmaf(r, vr, yr[it]);
            yr[it] = fmaf(-i, vi, yr[it]);
            yi[it] = fmaf(r, vi, yi[it]);
            yi[it] = fmaf(i, vr, yi[it]);
        }
    }

    // vectorized store (n0 is a multiple of 4; N is a multiple of SPB here,
    // guarded anyway)
    if (n0 + ITER <= N) {
        float4 vr4 = make_float4(yr[0], yr[1], yr[2], yr[3]);
        float4 vi4 = make_float4(yi[0], yi[1], yi[2], yi[3]);
        *reinterpret_cast<float4*>(out + n0) = vr4;
        *reinterpret_cast<float4*>(out + N + n0) = vi4;
    } else {
#pragma unroll
        for (int it = 0; it < ITER; ++it) {
            int n = n0 + it;
            if (n < N) { out[n] = yr[it]; out[N + n] = yi[it]; }
        }
    }
}

extern "C" void kernel_launch(void* const* d_in, const int* in_sizes, int n_in,
                              void* d_out, int out_size) {
    const float* x_re = (const float*)d_in[0];
    const float* x_im = (const float*)d_in[1];
    const float* a_re = (const float*)d_in[2];
    const float* a_im = (const float*)d_in[3];
    const float* b_re = (const float*)d_in[4];
    const float* b_im = (const float*)d_in[5];
    const float* c_re = (const float*)d_in[6];
    const float* c_im = (const float*)d_in[7];
    float* out = (float*)d_out;
    const int N = in_sizes[0];

    const int grid = (N + SPB - 1) / SPB;
    gmp_kernel<<<grid, TPB>>>(x_re, x_im, a_re, a_im, b_re, b_im,
                              c_re, c_im, out, N);
}